// round 1
// baseline (speedup 1.0000x reference)
#include <cuda_runtime.h>

#define BB 4
#define HH 16
#define SS 4096
#define DD 64
#define NBH (BB*HH)
#define EPS 1e-6f

// Scratch (device globals — no allocation allowed)
__device__ float g_kv[NBH * DD * DD];     // [bh][d][f]
__device__ float g_ksum[NBH * DD];        // [bh][d]
__device__ int   g_mask_fmt;              // 0 = 4-byte elements (int32/float32), 1 = 1-byte (bool/uint8)

// ---------- helpers ----------
__device__ __forceinline__ float fmap(float x) {
    // elu(x)+1 == x>0 ? x+1 : exp(x)
    return x > 0.0f ? x + 1.0f : __expf(x);
}

__device__ __forceinline__ void fma2(unsigned long long &acc,
                                     unsigned long long a,
                                     unsigned long long b) {
    asm("fma.rn.f32x2 %0, %1, %2, %0;" : "+l"(acc) : "l"(a), "l"(b));
}

__device__ __forceinline__ unsigned long long packf2(float x, float y) {
    unsigned long long r;
    asm("mov.b64 %0, {%1, %2};" : "=l"(r) : "f"(x), "f"(y));
    return r;
}

__device__ __forceinline__ float2 unpackf2(unsigned long long v) {
    float2 r;
    asm("mov.b64 {%0, %1}, %2;" : "=f"(r.x), "=f"(r.y) : "l"(v));
    return r;
}

__device__ __forceinline__ float get_valid(const void* mask, int fmt, int idx) {
    if (fmt) {
        return ((const unsigned char*)mask)[idx] == 0 ? 1.0f : 0.0f;
    }
    return ((const unsigned int*)mask)[idx] == 0u ? 1.0f : 0.0f;
}

// ---------- kernels ----------
__global__ void zero_kernel() {
    int idx = blockIdx.x * blockDim.x + threadIdx.x;
    if (idx < NBH * DD * DD) g_kv[idx] = 0.0f;
    if (idx < NBH * DD)      g_ksum[idx] = 0.0f;
    if (idx == 0)            g_mask_fmt = 0;
}

// Detect mask element width: scan first 4096 32-bit words (16 KB — in bounds
// for both layouts). int32 bools are {0,1}; float32 bools are {0, 0x3F800000};
// byte-packed bools produce other word values w.h.p. (25% ones over 16K bytes).
__global__ void detect_kernel(const unsigned int* __restrict__ mask) {
    int idx = blockIdx.x * blockDim.x + threadIdx.x;  // 4096 threads
    unsigned int w = mask[idx];
    if (w != 0u && w != 1u && w != 0x3F800000u) atomicOr(&g_mask_fmt, 1);
}

// Pass 1: kv[bh] += sum_s phi(k[s]) (x) v[s];  ksum[bh] += sum_s phi(k[s])
// grid (8 s-chunks, 64 bh), 256 threads. Each thread owns a 4(d) x 4(f)
// register tile, f packed in pairs for fma.rn.f32x2.
__global__ void __launch_bounds__(256)
pass1_kernel(const float* __restrict__ kk, const float* __restrict__ vv,
             const void* __restrict__ mask) {
    __shared__ float ksh[32 * 64];
    __shared__ float vsh[32 * 64];

    const int bh  = blockIdx.y;
    const int s0  = blockIdx.x * 512;
    const int tid = threadIdx.x;
    const int fmt = g_mask_fmt;
    const int b   = bh >> 4;
    const int i   = tid & 15;      // d group
    const int j   = tid >> 4;      // f group

    unsigned long long acc[4][2];
#pragma unroll
    for (int a = 0; a < 4; a++)
#pragma unroll
        for (int c = 0; c < 2; c++) acc[a][c] = 0ull;
    float ks0 = 0.f, ks1 = 0.f, ks2 = 0.f, ks3 = 0.f;

    const float4* kg = (const float4*)(kk + (size_t)bh * SS * DD);
    const float4* vg = (const float4*)(vv + (size_t)bh * SS * DD);

    for (int st = 0; st < 16; st++) {
        const int sbase = s0 + st * 32;
        __syncthreads();
#pragma unroll
        for (int it = 0; it < 2; it++) {
            int vi = it * 256 + tid;        // float4 index in 32x64 tile
            int sl = vi >> 4;               // 16 float4 per row
            int c4 = vi & 15;
            float valid = get_valid(mask, fmt, b * SS + sbase + sl);
            float4 k4 = kg[(size_t)(sbase + sl) * 16 + c4];
            float4 v4 = vg[(size_t)(sbase + sl) * 16 + c4];
            k4.x = fmap(k4.x) * valid;
            k4.y = fmap(k4.y) * valid;
            k4.z = fmap(k4.z) * valid;
            k4.w = fmap(k4.w) * valid;
            ((float4*)ksh)[vi] = k4;
            ((float4*)vsh)[vi] = v4;
        }
        __syncthreads();

#pragma unroll 8
        for (int sl = 0; sl < 32; sl++) {
            const float* kr = ksh + sl * 64;
            float2 ka = *(const float2*)(kr + 2 * i);
            float2 kb = *(const float2*)(kr + 2 * i + 32);
            unsigned long long va =
                *(const unsigned long long*)(vsh + sl * 64 + 2 * j);
            unsigned long long vb =
                *(const unsigned long long*)(vsh + sl * 64 + 2 * j + 32);
            unsigned long long p;
            p = packf2(ka.x, ka.x); fma2(acc[0][0], p, va); fma2(acc[0][1], p, vb);
            p = packf2(ka.y, ka.y); fma2(acc[1][0], p, va); fma2(acc[1][1], p, vb);
            p = packf2(kb.x, kb.x); fma2(acc[2][0], p, va); fma2(acc[2][1], p, vb);
            p = packf2(kb.y, kb.y); fma2(acc[3][0], p, va); fma2(acc[3][1], p, vb);
            if (j == 0) { ks0 += ka.x; ks1 += ka.y; ks2 += kb.x; ks3 += kb.y; }
        }
    }

    const int ds[4] = {2 * i, 2 * i + 1, 2 * i + 32, 2 * i + 33};
    const int fs[2] = {2 * j, 2 * j + 32};
    float* kvg = g_kv + bh * DD * DD;
#pragma unroll
    for (int a = 0; a < 4; a++)
#pragma unroll
        for (int c = 0; c < 2; c++) {
            float2 r = unpackf2(acc[a][c]);
            atomicAdd(&kvg[ds[a] * 64 + fs[c]],     r.x);
            atomicAdd(&kvg[ds[a] * 64 + fs[c] + 1], r.y);
        }
    if (j == 0) {
        float* kss = g_ksum + bh * DD;
        atomicAdd(&kss[2 * i],      ks0);
        atomicAdd(&kss[2 * i + 1],  ks1);
        atomicAdd(&kss[2 * i + 32], ks2);
        atomicAdd(&kss[2 * i + 33], ks3);
    }
}

// Pass 2: out[t] = (phi(q[t]) @ kv) / (phi(q[t]) . ksum + eps)
// grid (64 t-tiles, 64 bh), 256 threads. 4 threads per token, 16 f each.
__global__ void __launch_bounds__(256)
pass2_kernel(const float* __restrict__ qq, float* __restrict__ out) {
    __shared__ float qsh[64 * 65];   // padded rows (stride 65) to avoid conflicts
    __shared__ float kvsh[64 * 64];
    __shared__ float kss[64];

    const int bh  = blockIdx.y;
    const int t0  = blockIdx.x * 64;
    const int tid = threadIdx.x;

    const float4* kvg = (const float4*)(g_kv + bh * DD * DD);
#pragma unroll
    for (int it = 0; it < 4; it++)
        ((float4*)kvsh)[it * 256 + tid] = kvg[it * 256 + tid];
    if (tid < 64) kss[tid] = g_ksum[bh * DD + tid];

    const float4* qg = (const float4*)(qq + (size_t)bh * SS * DD + (size_t)t0 * DD);
#pragma unroll
    for (int it = 0; it < 4; it++) {
        int vi = it * 256 + tid;       // float4 idx, 16 per row
        float4 x = qg[vi];
        x.x = fmap(x.x); x.y = fmap(x.y); x.z = fmap(x.z); x.w = fmap(x.w);
        int row = vi >> 4, c = (vi & 15) * 4;
        float* dst = qsh + row * 65 + c;
        dst[0] = x.x; dst[1] = x.y; dst[2] = x.z; dst[3] = x.w;
    }
    __syncthreads();

    const int ty = tid >> 2;          // token within tile
    const int tx = tid & 3;           // f block: 16 floats
    const float* qr = qsh + ty * 65;

    float z = EPS;
#pragma unroll
    for (int d = 0; d < 64; d++) z += qr[d] * kss[d];

    unsigned long long acc[8];
#pragma unroll
    for (int a = 0; a < 8; a++) acc[a] = 0ull;

#pragma unroll 16
    for (int d = 0; d < 64; d++) {
        float qv = qr[d];
        unsigned long long qp = packf2(qv, qv);
        const ulonglong2* kr = (const ulonglong2*)(kvsh + d * 64 + tx * 16);
        ulonglong2 u0 = kr[0], u1 = kr[1], u2 = kr[2], u3 = kr[3];
        fma2(acc[0], qp, u0.x); fma2(acc[1], qp, u0.y);
        fma2(acc[2], qp, u1.x); fma2(acc[3], qp, u1.y);
        fma2(acc[4], qp, u2.x); fma2(acc[5], qp, u2.y);
        fma2(acc[6], qp, u3.x); fma2(acc[7], qp, u3.y);
    }

    const float invz = 1.0f / z;
    float* og = out + (size_t)bh * SS * DD + (size_t)(t0 + ty) * DD + tx * 16;
#pragma unroll
    for (int p = 0; p < 4; p++) {
        float2 a = unpackf2(acc[2 * p]);
        float2 bv = unpackf2(acc[2 * p + 1]);
        float4 o;
        o.x = a.x * invz;  o.y = a.y * invz;
        o.z = bv.x * invz; o.w = bv.y * invz;
        ((float4*)og)[p] = o;
    }
}

extern "C" void kernel_launch(void* const* d_in, const int* in_sizes, int n_in,
                              void* d_out, int out_size) {
    const float* q = (const float*)d_in[0];
    const float* k = (const float*)d_in[1];
    const float* v = (const float*)d_in[2];
    const void*  m = d_in[3];
    float* out = (float*)d_out;

    zero_kernel<<<1024, 256>>>();
    detect_kernel<<<16, 256>>>((const unsigned int*)m);
    pass1_kernel<<<dim3(8, NBH), 256>>>(k, v, m);
    pass2_kernel<<<dim3(SS / 64, NBH), 256>>>(q, out);
}

// round 2
// speedup vs baseline: 1.9315x; 1.9315x over previous
#include <cuda_runtime.h>

#define BB 4
#define HH 16
#define SS 4096
#define DD 64
#define NBH (BB*HH)
#define EPS 1e-6f

// Scratch (device globals — no allocation allowed)
__device__ float g_kv[NBH * DD * DD];     // [bh][d][f]
__device__ float g_ksum[NBH * DD];        // [bh][d]
__device__ int   g_mask_fmt;              // 0 = 4-byte elements, 1 = 1-byte

// ---------- helpers ----------
__device__ __forceinline__ float fmap(float x) {
    return x > 0.0f ? x + 1.0f : __expf(x);
}

__device__ __forceinline__ void fma2(unsigned long long &acc,
                                     unsigned long long a,
                                     unsigned long long b) {
    asm("fma.rn.f32x2 %0, %1, %2, %0;" : "+l"(acc) : "l"(a), "l"(b));
}

__device__ __forceinline__ unsigned long long packf2(float x, float y) {
    unsigned long long r;
    asm("mov.b64 %0, {%1, %2};" : "=l"(r) : "f"(x), "f"(y));
    return r;
}

__device__ __forceinline__ float2 unpackf2(unsigned long long v) {
    float2 r;
    asm("mov.b64 {%0, %1}, %2;" : "=f"(r.x), "=f"(r.y) : "l"(v));
    return r;
}

__device__ __forceinline__ float get_valid(const void* mask, int fmt, int idx) {
    if (fmt) return ((const unsigned char*)mask)[idx] == 0 ? 1.0f : 0.0f;
    return ((const unsigned int*)mask)[idx] == 0u ? 1.0f : 0.0f;
}

// ---------- kernels ----------
__global__ void zero_kernel() {
    int idx = blockIdx.x * blockDim.x + threadIdx.x;
    if (idx < NBH * DD * DD) g_kv[idx] = 0.0f;
    if (idx < NBH * DD)      g_ksum[idx] = 0.0f;
    if (idx == 0)            g_mask_fmt = 0;
}

__global__ void detect_kernel(const unsigned int* __restrict__ mask) {
    int idx = blockIdx.x * blockDim.x + threadIdx.x;  // 4096 threads
    unsigned int w = mask[idx];
    if (w != 0u && w != 1u && w != 0x3F800000u) atomicOr(&g_mask_fmt, 1);
}

// Pass 1: kv[bh] += sum_s phi(k[s]) (x) v[s];  ksum[bh] += sum_s phi(k[s])
// grid (16 s-chunks, 64 bh), 256 threads; thread tile 4(d) x 4(f).
__global__ void __launch_bounds__(256)
pass1_kernel(const float* __restrict__ kk, const float* __restrict__ vv,
             const void* __restrict__ mask) {
    __shared__ float ksh[32 * 64];
    __shared__ float vsh[32 * 64];

    const int bh  = blockIdx.y;
    const int s0  = blockIdx.x * 256;
    const int tid = threadIdx.x;
    const int fmt = g_mask_fmt;
    const int b   = bh >> 4;
    const int i   = tid & 15;      // d group
    const int j   = tid >> 4;      // f group

    unsigned long long acc[4][2];
#pragma unroll
    for (int a = 0; a < 4; a++)
#pragma unroll
        for (int c = 0; c < 2; c++) acc[a][c] = 0ull;
    float ks0 = 0.f, ks1 = 0.f, ks2 = 0.f, ks3 = 0.f;

    const float4* kg = (const float4*)(kk + (size_t)bh * SS * DD);
    const float4* vg = (const float4*)(vv + (size_t)bh * SS * DD);

    for (int st = 0; st < 8; st++) {
        const int sbase = s0 + st * 32;
        __syncthreads();
#pragma unroll
        for (int it = 0; it < 2; it++) {
            int vi = it * 256 + tid;
            int sl = vi >> 4;
            int c4 = vi & 15;
            float valid = get_valid(mask, fmt, b * SS + sbase + sl);
            float4 k4 = kg[(size_t)(sbase + sl) * 16 + c4];
            float4 v4 = vg[(size_t)(sbase + sl) * 16 + c4];
            k4.x = fmap(k4.x) * valid;
            k4.y = fmap(k4.y) * valid;
            k4.z = fmap(k4.z) * valid;
            k4.w = fmap(k4.w) * valid;
            ((float4*)ksh)[vi] = k4;
            ((float4*)vsh)[vi] = v4;
        }
        __syncthreads();

#pragma unroll 8
        for (int sl = 0; sl < 32; sl++) {
            const float* kr = ksh + sl * 64;
            float2 ka = *(const float2*)(kr + 2 * i);
            float2 kb = *(const float2*)(kr + 2 * i + 32);
            unsigned long long va =
                *(const unsigned long long*)(vsh + sl * 64 + 2 * j);
            unsigned long long vb =
                *(const unsigned long long*)(vsh + sl * 64 + 2 * j + 32);
            unsigned long long p;
            p = packf2(ka.x, ka.x); fma2(acc[0][0], p, va); fma2(acc[0][1], p, vb);
            p = packf2(ka.y, ka.y); fma2(acc[1][0], p, va); fma2(acc[1][1], p, vb);
            p = packf2(kb.x, kb.x); fma2(acc[2][0], p, va); fma2(acc[2][1], p, vb);
            p = packf2(kb.y, kb.y); fma2(acc[3][0], p, va); fma2(acc[3][1], p, vb);
            if (j == 0) { ks0 += ka.x; ks1 += ka.y; ks2 += kb.x; ks3 += kb.y; }
        }
    }

    const int ds[4] = {2 * i, 2 * i + 1, 2 * i + 32, 2 * i + 33};
    const int fs[2] = {2 * j, 2 * j + 32};
    float* kvg = g_kv + bh * DD * DD;
#pragma unroll
    for (int a = 0; a < 4; a++)
#pragma unroll
        for (int c = 0; c < 2; c++) {
            float2 r = unpackf2(acc[a][c]);
            atomicAdd(&kvg[ds[a] * 64 + fs[c]],     r.x);
            atomicAdd(&kvg[ds[a] * 64 + fs[c] + 1], r.y);
        }
    if (j == 0) {
        float* kss = g_ksum + bh * DD;
        atomicAdd(&kss[2 * i],      ks0);
        atomicAdd(&kss[2 * i + 1],  ks1);
        atomicAdd(&kss[2 * i + 32], ks2);
        atomicAdd(&kss[2 * i + 33], ks3);
    }
}

// Pass 2: out[t] = (phi(q[t]) @ kv) / (phi(q[t]) . ksum + eps)
// Block = 128 tokens x 64 f, 256 threads, thread tile 4t x 8f.
#define QP 68   // padded row stride for qsh
__global__ void __launch_bounds__(256)
pass2_kernel(const float* __restrict__ qq, float* __restrict__ out) {
    __shared__ float qsh[128 * QP];
    __shared__ float kvsh[64 * 64];
    __shared__ float kss[64];
    __shared__ float psh[256];

    const int bh  = blockIdx.y;
    const int t0  = blockIdx.x * 128;
    const int tid = threadIdx.x;

    // load kv (16KB) and ksum
    const float4* kvg = (const float4*)(g_kv + bh * DD * DD);
#pragma unroll
    for (int it = 0; it < 4; it++)
        ((float4*)kvsh)[it * 256 + tid] = kvg[it * 256 + tid];
    if (tid < 64) kss[tid] = g_ksum[bh * DD + tid];

    // load q tile (128x64), apply feature map
    const float4* qg = (const float4*)(qq + (size_t)bh * SS * DD + (size_t)t0 * DD);
#pragma unroll
    for (int it = 0; it < 8; it++) {
        int vi = it * 256 + tid;       // float4 idx, 16 per row
        float4 x = qg[vi];
        x.x = fmap(x.x); x.y = fmap(x.y); x.z = fmap(x.z); x.w = fmap(x.w);
        int row = vi >> 4, c = (vi & 15) * 4;
        *(float4*)(qsh + row * QP + c) = x;
    }
    __syncthreads();

    // z partials: thread handles token tid>>1, half (tid&1) of d
    {
        int tp = tid >> 1;
        int off = (tid & 1) * 32;
        const float* qr = qsh + tp * QP + off;
        const unsigned long long* ks2 = (const unsigned long long*)(kss + off);
        unsigned long long zacc = 0ull;
#pragma unroll
        for (int u = 0; u < 16; u++) {
            unsigned long long qp = *(const unsigned long long*)(qr + 2 * u);
            fma2(zacc, qp, ks2[u]);
        }
        float2 zr = unpackf2(zacc);
        psh[tid] = zr.x + zr.y;
    }

    // main GEMM: acc[4 tokens][4 f-pairs]
    const int ty = tid >> 3;           // 0..31 -> tokens ty*4..+3
    const int tx = tid & 7;            // 0..7  -> f = tx*8..+7
    const float* qbase = qsh + (ty * 4) * QP;
    const int f0 = tx * 8;

    unsigned long long acc[4][4];
#pragma unroll
    for (int r = 0; r < 4; r++)
#pragma unroll
        for (int p = 0; p < 4; p++) acc[r][p] = 0ull;

#pragma unroll 4
    for (int dc = 0; dc < 16; dc++) {
        const int d = dc * 4;
        float4 qv[4];
#pragma unroll
        for (int r = 0; r < 4; r++)
            qv[r] = *(const float4*)(qbase + r * QP + d);
#pragma unroll
        for (int dd = 0; dd < 4; dd++) {
            const float* kr = kvsh + (d + dd) * 64 + f0;
            ulonglong2 kva = *(const ulonglong2*)(kr);
            ulonglong2 kvb = *(const ulonglong2*)(kr + 4);
            float qs[4] = {qv[0].x, qv[1].x, qv[2].x, qv[3].x};
            if (dd == 1) { qs[0]=qv[0].y; qs[1]=qv[1].y; qs[2]=qv[2].y; qs[3]=qv[3].y; }
            if (dd == 2) { qs[0]=qv[0].z; qs[1]=qv[1].z; qs[2]=qv[2].z; qs[3]=qv[3].z; }
            if (dd == 3) { qs[0]=qv[0].w; qs[1]=qv[1].w; qs[2]=qv[2].w; qs[3]=qv[3].w; }
#pragma unroll
            for (int r = 0; r < 4; r++) {
                unsigned long long qp = packf2(qs[r], qs[r]);
                fma2(acc[r][0], qp, kva.x);
                fma2(acc[r][1], qp, kva.y);
                fma2(acc[r][2], qp, kvb.x);
                fma2(acc[r][3], qp, kvb.y);
            }
        }
    }
    __syncthreads();

    // epilogue
#pragma unroll
    for (int r = 0; r < 4; r++) {
        const int t = ty * 4 + r;
        const float z = psh[2 * t] + psh[2 * t + 1] + EPS;
        const float invz = 1.0f / z;
        float* og = out + (size_t)bh * SS * DD + (size_t)(t0 + t) * DD + f0;
        float2 a0 = unpackf2(acc[r][0]);
        float2 a1 = unpackf2(acc[r][1]);
        float2 a2 = unpackf2(acc[r][2]);
        float2 a3 = unpackf2(acc[r][3]);
        float4 o0, o1;
        o0.x = a0.x * invz; o0.y = a0.y * invz;
        o0.z = a1.x * invz; o0.w = a1.y * invz;
        o1.x = a2.x * invz; o1.y = a2.y * invz;
        o1.z = a3.x * invz; o1.w = a3.y * invz;
        ((float4*)og)[0] = o0;
        ((float4*)og)[1] = o1;
    }
}

extern "C" void kernel_launch(void* const* d_in, const int* in_sizes, int n_in,
                              void* d_out, int out_size) {
    const float* q = (const float*)d_in[0];
    const float* k = (const float*)d_in[1];
    const float* v = (const float*)d_in[2];
    const void*  m = d_in[3];
    float* out = (float*)d_out;

    zero_kernel<<<1024, 256>>>();
    detect_kernel<<<16, 256>>>((const unsigned int*)m);
    pass1_kernel<<<dim3(16, NBH), 256>>>(k, v, m);
    pass2_kernel<<<dim3(SS / 128, NBH), 256>>>(q, out);
}

// round 3
// speedup vs baseline: 2.1022x; 1.0884x over previous
#include <cuda_runtime.h>

#define BB 4
#define HH 16
#define SS 4096
#define DD 64
#define NBH (BB*HH)
#define EPS 1e-6f

__device__ float g_kv[NBH * DD * DD];     // [bh][d][f]
__device__ float g_ksum[NBH * DD];        // [bh][d]
__device__ int   g_mask_fmt;              // 0 = 4-byte elements, 1 = 1-byte

// ---------- helpers ----------
__device__ __forceinline__ float fmap(float x) {
    return x > 0.0f ? x + 1.0f : __expf(x);
}

__device__ __forceinline__ void fma2(unsigned long long &acc,
                                     unsigned long long a,
                                     unsigned long long b) {
    asm("fma.rn.f32x2 %0, %1, %2, %0;" : "+l"(acc) : "l"(a), "l"(b));
}

__device__ __forceinline__ unsigned long long packf2(float x, float y) {
    unsigned long long r;
    asm("mov.b64 %0, {%1, %2};" : "=l"(r) : "f"(x), "f"(y));
    return r;
}

__device__ __forceinline__ float2 unpackf2(unsigned long long v) {
    float2 r;
    asm("mov.b64 {%0, %1}, %2;" : "=f"(r.x), "=f"(r.y) : "l"(v));
    return r;
}

__device__ __forceinline__ float get_valid(const void* mask, int fmt, int idx) {
    if (fmt) return ((const unsigned char*)mask)[idx] == 0 ? 1.0f : 0.0f;
    return ((const unsigned int*)mask)[idx] == 0u ? 1.0f : 0.0f;
}

// ---------- small kernels ----------
__global__ void zero_kernel() {
    int idx = blockIdx.x * blockDim.x + threadIdx.x;
    if (idx < NBH * DD * DD) g_kv[idx] = 0.0f;
    if (idx < NBH * DD)      g_ksum[idx] = 0.0f;
    if (idx == 0)            g_mask_fmt = 0;
}

__global__ void detect_kernel(const unsigned int* __restrict__ mask) {
    int idx = blockIdx.x * blockDim.x + threadIdx.x;  // 4096 threads
    unsigned int w = mask[idx];
    if (w != 0u && w != 1u && w != 0x3F800000u) atomicOr(&g_mask_fmt, 1);
}

// ---------- Pass 1 ----------
// grid (8, 64), 128 threads = 2 groups of 64. Each group: 8d x 8f thread tile,
// processes half the tokens of the 512-token chunk. In-block reduce, then atomics.
__global__ void __launch_bounds__(128)
pass1_kernel(const float* __restrict__ kk, const float* __restrict__ vv,
             const void* __restrict__ mask) {
    __shared__ float sm[4096];     // ksh = sm[0..2048), vsh = sm[2048..4096)
    float* ksh = sm;
    float* vsh = sm + 2048;

    const int bh  = blockIdx.y;
    const int s0  = blockIdx.x * 512;
    const int tid = threadIdx.x;
    const int g   = tid >> 6;        // group 0/1
    const int lt  = tid & 63;
    const int i   = lt & 7;          // d: {4i..4i+3, 32+4i..32+4i+3}
    const int j   = lt >> 3;         // f: {4j..4j+3, 32+4j..32+4j+3}
    const int fmt = g_mask_fmt;
    const int b   = bh >> 4;

    unsigned long long acc[8][4];
#pragma unroll
    for (int a = 0; a < 8; a++)
#pragma unroll
        for (int p = 0; p < 4; p++) acc[a][p] = 0ull;
    float ks[8];
#pragma unroll
    for (int a = 0; a < 8; a++) ks[a] = 0.f;

    const float4* kg = (const float4*)(kk + (size_t)bh * SS * DD);
    const float4* vg = (const float4*)(vv + (size_t)bh * SS * DD);

    for (int st = 0; st < 16; st++) {
        const int sbase = s0 + st * 32;
        __syncthreads();
#pragma unroll
        for (int it = 0; it < 4; it++) {
            int vi = it * 128 + tid;        // float4 index in 32x64 tile
            int sl = vi >> 4;
            int c4 = vi & 15;
            float valid = get_valid(mask, fmt, b * SS + sbase + sl);
            float4 k4 = kg[(size_t)(sbase + sl) * 16 + c4];
            float4 v4 = vg[(size_t)(sbase + sl) * 16 + c4];
            k4.x = fmap(k4.x) * valid;
            k4.y = fmap(k4.y) * valid;
            k4.z = fmap(k4.z) * valid;
            k4.w = fmap(k4.w) * valid;
            ((float4*)ksh)[vi] = k4;
            ((float4*)vsh)[vi] = v4;
        }
        __syncthreads();

#pragma unroll 4
        for (int m = 0; m < 16; m++) {
            const int sl = g * 16 + m;
            float4 ka = *(const float4*)(ksh + sl * 64 + 4 * i);
            float4 kb = *(const float4*)(ksh + sl * 64 + 32 + 4 * i);
            ulonglong2 va = *(const ulonglong2*)(vsh + sl * 64 + 4 * j);
            ulonglong2 vb = *(const ulonglong2*)(vsh + sl * 64 + 32 + 4 * j);
            float kd[8] = {ka.x, ka.y, ka.z, ka.w, kb.x, kb.y, kb.z, kb.w};
#pragma unroll
            for (int a = 0; a < 8; a++) {
                unsigned long long qp = packf2(kd[a], kd[a]);
                fma2(acc[a][0], qp, va.x);
                fma2(acc[a][1], qp, va.y);
                fma2(acc[a][2], qp, vb.x);
                fma2(acc[a][3], qp, vb.y);
            }
            if (j == 0) {
#pragma unroll
                for (int a = 0; a < 8; a++) ks[a] += kd[a];
            }
        }
    }

    // in-block reduce group1 -> group0, then atomics
    __syncthreads();
    unsigned long long* buf = (unsigned long long*)sm;   // 2048 ull = 16KB
    if (g == 1) {
#pragma unroll
        for (int a = 0; a < 8; a++)
#pragma unroll
            for (int p = 0; p < 4; p++) buf[lt * 32 + a * 4 + p] = acc[a][p];
    }
    __syncthreads();
    if (g == 0) {
        float* kvg = g_kv + bh * DD * DD;
#pragma unroll
        for (int a = 0; a < 8; a++) {
            const int d = (a < 4) ? (4 * i + a) : (32 + 4 * i + a - 4);
#pragma unroll
            for (int p = 0; p < 4; p++) {
                const int f = (p < 2) ? (4 * j + 2 * p) : (32 + 4 * j + 2 * (p - 2));
                float2 r = unpackf2(acc[a][p]);
                float2 o = unpackf2(buf[lt * 32 + a * 4 + p]);
                atomicAdd(&kvg[d * 64 + f],     r.x + o.x);
                atomicAdd(&kvg[d * 64 + f + 1], r.y + o.y);
            }
        }
    }
    if (j == 0) {
        float* kss = g_ksum + bh * DD;
#pragma unroll
        for (int a = 0; a < 8; a++) {
            const int d = (a < 4) ? (4 * i + a) : (32 + 4 * i + a - 4);
            atomicAdd(&kss[d], ks[a]);
        }
    }
}

// ---------- Pass 2 ----------
// grid (32, 64), 128 threads, 128 tokens/block, thread tile 8t x 8f.
// q stored transposed qsh[d][t] for contiguous broadcast-friendly reads.
__global__ void __launch_bounds__(128)
pass2_kernel(const float* __restrict__ qq, float* __restrict__ out) {
    __shared__ float qsh[64 * 128];   // [d][t]
    __shared__ float kvsh[64 * 64];   // [d][f]
    __shared__ float kss[64];
    __shared__ float zsh[128];

    const int bh  = blockIdx.y;
    const int t0  = blockIdx.x * 128;
    const int tid = threadIdx.x;

    // load kv (16KB) + ksum
    const float4* kvg = (const float4*)(g_kv + bh * DD * DD);
#pragma unroll
    for (int it = 0; it < 8; it++)
        ((float4*)kvsh)[it * 128 + tid] = kvg[it * 128 + tid];
    if (tid < 16)
        ((float4*)kss)[tid] = ((const float4*)(g_ksum + bh * DD))[tid];

    // load this thread's token row (token = tid), apply feature map
    const float4* qg = (const float4*)(qq + (size_t)bh * SS * DD + (size_t)t0 * DD);
    float4 qr[16];
#pragma unroll
    for (int c = 0; c < 16; c++) {
        float4 x = qg[tid * 16 + c];
        x.x = fmap(x.x); x.y = fmap(x.y); x.z = fmap(x.z); x.w = fmap(x.w);
        qr[c] = x;
    }
    __syncthreads();   // kss + kvsh visible

    // z for token tid
    float z = EPS;
#pragma unroll
    for (int c = 0; c < 16; c++) {
        z += qr[c].x * kss[4 * c] + qr[c].y * kss[4 * c + 1]
           + qr[c].z * kss[4 * c + 2] + qr[c].w * kss[4 * c + 3];
    }
    zsh[tid] = 1.0f / z;

    // store q transposed
#pragma unroll
    for (int c = 0; c < 16; c++) {
        qsh[(4 * c + 0) * 128 + tid] = qr[c].x;
        qsh[(4 * c + 1) * 128 + tid] = qr[c].y;
        qsh[(4 * c + 2) * 128 + tid] = qr[c].z;
        qsh[(4 * c + 3) * 128 + tid] = qr[c].w;
    }
    __syncthreads();

    // main GEMM: tokens {4ty+r, 64+4ty+r}, f {4tx.., 32+4tx..}
    const int ty = tid >> 3;   // 0..15
    const int tx = tid & 7;    // 0..7

    unsigned long long acc[8][4];
#pragma unroll
    for (int r = 0; r < 8; r++)
#pragma unroll
        for (int p = 0; p < 4; p++) acc[r][p] = 0ull;

#pragma unroll 4
    for (int d = 0; d < 64; d++) {
        float4 qa = *(const float4*)(qsh + d * 128 + 4 * ty);
        float4 qb = *(const float4*)(qsh + d * 128 + 64 + 4 * ty);
        ulonglong2 va = *(const ulonglong2*)(kvsh + d * 64 + 4 * tx);
        ulonglong2 vb = *(const ulonglong2*)(kvsh + d * 64 + 32 + 4 * tx);
        float qs[8] = {qa.x, qa.y, qa.z, qa.w, qb.x, qb.y, qb.z, qb.w};
#pragma unroll
        for (int r = 0; r < 8; r++) {
            unsigned long long qp = packf2(qs[r], qs[r]);
            fma2(acc[r][0], qp, va.x);
            fma2(acc[r][1], qp, va.y);
            fma2(acc[r][2], qp, vb.x);
            fma2(acc[r][3], qp, vb.y);
        }
    }

    // epilogue
#pragma unroll
    for (int r = 0; r < 8; r++) {
        const int t = (r < 4) ? (4 * ty + r) : (64 + 4 * ty + r - 4);
        const float invz = zsh[t];
        float* og = out + (size_t)bh * SS * DD + (size_t)(t0 + t) * DD;
        float2 a0 = unpackf2(acc[r][0]);
        float2 a1 = unpackf2(acc[r][1]);
        float2 a2 = unpackf2(acc[r][2]);
        float2 a3 = unpackf2(acc[r][3]);
        float4 o0, o1;
        o0.x = a0.x * invz; o0.y = a0.y * invz;
        o0.z = a1.x * invz; o0.w = a1.y * invz;
        o1.x = a2.x * invz; o1.y = a2.y * invz;
        o1.z = a3.x * invz; o1.w = a3.y * invz;
        *(float4*)(og + 4 * tx)      = o0;
        *(float4*)(og + 32 + 4 * tx) = o1;
    }
}

extern "C" void kernel_launch(void* const* d_in, const int* in_sizes, int n_in,
                              void* d_out, int out_size) {
    const float* q = (const float*)d_in[0];
    const float* k = (const float*)d_in[1];
    const float* v = (const float*)d_in[2];
    const void*  m = d_in[3];
    float* out = (float*)d_out;

    zero_kernel<<<1024, 256>>>();
    detect_kernel<<<16, 256>>>((const unsigned int*)m);
    pass1_kernel<<<dim3(8, NBH), 128>>>(k, v, m);
    pass2_kernel<<<dim3(SS / 128, NBH), 128>>>(q, out);
}